// round 12
// baseline (speedup 1.0000x reference)
#include <cuda_runtime.h>
#include <math.h>

#define D 512
#define V 17
#define MAX_SEGS 64
#define EPAD 20
#define KS 4            // k-slices in GEMM1
#define KSL 128
#define TPB 512

// Scratch (allocation-free, graph-safe).
__device__ float g_part1[KS][V][D];        // partial E@W1
__device__ int   g_hist[MAX_SEGS][V];      // per-segment token counts

// k1 shared scratch (max member 34816 B)
union SmemU {
    float etr[KSL * EPAD];      // transposed E k-slice (10240B)
    float red[16 * V * 32];     // split-slice reduction (34816B)
    int   cnt[16 * 32];         // per-warp histograms
};

// ---------------------------------------------------------------------------
// k1: CTAs 0..63: partial GEMM1 (jt x ks = 16 x 4). CTAs 64..: histograms.
// (identical to the R9 kernel that measured 5.5us)
// ---------------------------------------------------------------------------
__global__ void __launch_bounds__(TPB, 1)
k1(const float* __restrict__ E, const float* __restrict__ W1,
   const int* __restrict__ tok, const int* __restrict__ cu, int n_segs) {
    __shared__ SmemU sm;
    const int bid = blockIdx.x;
    const int tid = threadIdx.x;

    if (bid < 64) {
        const int jt = bid >> 2;
        const int ks = bid & 3;
        const int tx = tid & 31;
        const int ty = tid >> 5;

        // stage E k-slice transposed: one float4 LDG per thread (+tail)
        const float4* E4 = (const float4*)E;
        if (tid < V * 32) {
            const int v = tid >> 5;
            const int q = tid & 31;
            const float4 e = E4[v * (D / 4) + ks * 32 + q];
            const int kl = q * 4;
            sm.etr[(kl + 0) * EPAD + v] = e.x;
            sm.etr[(kl + 1) * EPAD + v] = e.y;
            sm.etr[(kl + 2) * EPAD + v] = e.z;
            sm.etr[(kl + 3) * EPAD + v] = e.w;
        }
        if (tid < V * 32 - TPB) {
            const int i = TPB + tid;
            const int v = i >> 5;
            const int q = i & 31;
            const float4 e = E4[v * (D / 4) + ks * 32 + q];
            const int kl = q * 4;
            sm.etr[(kl + 0) * EPAD + v] = e.x;
            sm.etr[(kl + 1) * EPAD + v] = e.y;
            sm.etr[(kl + 2) * EPAD + v] = e.z;
            sm.etr[(kl + 3) * EPAD + v] = e.w;
        }
        __syncthreads();

        float acc[V];
#pragma unroll
        for (int v = 0; v < V; v++) acc[v] = 0.0f;

        const float* wp = W1 + (size_t)(ks * KSL + ty * 8) * D + jt * 32 + tx;
        float w[8];
#pragma unroll
        for (int kk = 0; kk < 8; kk++) w[kk] = wp[kk * D];

#pragma unroll
        for (int kk = 0; kk < 8; kk++) {
            const float* er = &sm.etr[(ty * 8 + kk) * EPAD];
            const float4 e0 = *(const float4*)(er);
            const float4 e1 = *(const float4*)(er + 4);
            const float4 e2 = *(const float4*)(er + 8);
            const float4 e3 = *(const float4*)(er + 12);
            const float  ee = er[16];
            const float  wv = w[kk];
            acc[0]  += e0.x * wv;  acc[1]  += e0.y * wv;
            acc[2]  += e0.z * wv;  acc[3]  += e0.w * wv;
            acc[4]  += e1.x * wv;  acc[5]  += e1.y * wv;
            acc[6]  += e1.z * wv;  acc[7]  += e1.w * wv;
            acc[8]  += e2.x * wv;  acc[9]  += e2.y * wv;
            acc[10] += e2.z * wv;  acc[11] += e2.w * wv;
            acc[12] += e3.x * wv;  acc[13] += e3.y * wv;
            acc[14] += e3.z * wv;  acc[15] += e3.w * wv;
            acc[16] += ee   * wv;
        }
        __syncthreads();

#pragma unroll
        for (int v = 0; v < V; v++) sm.red[(ty * V + v) * 32 + tx] = acc[v];
        __syncthreads();

        for (int o = tid; o < V * 32; o += TPB) {
            const int v = o >> 5;
            const int t = o & 31;
            float s = 0.0f;
#pragma unroll
            for (int sl = 0; sl < 16; sl++) s += sm.red[(sl * V + v) * 32 + t];
            g_part1[ks][v][jt * 32 + t] = s;
        }
        return;
    }

    const int s = bid - 64;
    if (s >= n_segs) return;
    const int start = cu[s];
    const int end = cu[s + 1];
    const int wid = tid >> 5;

    for (int i = tid; i < 16 * 32; i += TPB) sm.cnt[i] = 0;
    __syncthreads();
    for (int base = start + tid * 4; base < end; base += TPB * 4) {
        int t0 = -1, t1 = -1, t2 = -1, t3 = -1;
        if (base + 0 < end) t0 = tok[base + 0];
        if (base + 1 < end) t1 = tok[base + 1];
        if (base + 2 < end) t2 = tok[base + 2];
        if (base + 3 < end) t3 = tok[base + 3];
        if (t0 >= 0) atomicAdd(&sm.cnt[wid * 32 + t0], 1);
        if (t1 >= 0) atomicAdd(&sm.cnt[wid * 32 + t1], 1);
        if (t2 >= 0) atomicAdd(&sm.cnt[wid * 32 + t2], 1);
        if (t3 >= 0) atomicAdd(&sm.cnt[wid * 32 + t3], 1);
    }
    __syncthreads();
    if (tid < V) {
        int c = 0;
#pragma unroll
        for (int w = 0; w < 16; w++) c += sm.cnt[w * 32 + tid];
        g_hist[s][tid] = c;
    }
}

// ---------------------------------------------------------------------------
// k2: 64 CTAs x 8 output columns. Stage finalized gelu-mid from g_part1
// (R7-proven pattern), full-K GEMM2, deterministic 64-way reduce, segment
// mix + store. Static smem: 40960 + 2176 + 4608 + 256 = 48000 B.
// ---------------------------------------------------------------------------
__global__ void __launch_bounds__(TPB, 1)
k2(const float* __restrict__ W2, const float* __restrict__ b1,
   const float* __restrict__ b2, const int* __restrict__ cu,
   float* __restrict__ out, int n_segs) {
    __shared__ float etr[D * EPAD];
    __shared__ float Ht[V * 8 * 4];
    __shared__ float fcs[MAX_SEGS * 18];
    __shared__ float inv[MAX_SEGS];

    const int bid = blockIdx.x;
    const int tid = threadIdx.x;
    const int jl = tid & 7;
    const int ty = tid >> 3;
    const int jbase = bid * 8;

    // overlap: segment counts + inverse lengths
    {
        const int i0 = tid, i1 = tid + TPB, i2 = tid + 2 * TPB;
        int c0 = 0, c1 = 0, c2 = 0;
        if (i0 < n_segs * V) c0 = ((const int*)g_hist)[i0];
        if (i1 < n_segs * V) c1 = ((const int*)g_hist)[i1];
        if (i2 < n_segs * V) c2 = ((const int*)g_hist)[i2];
        if (i0 < n_segs * V) fcs[(i0 / V) * 18 + (i0 % V)] = (float)c0;
        if (i1 < n_segs * V) fcs[(i1 / V) * 18 + (i1 % V)] = (float)c1;
        if (i2 < n_segs * V) fcs[(i2 / V) * 18 + (i2 % V)] = (float)c2;
        if (tid < n_segs) inv[tid] = 1.0f / (float)(cu[tid + 1] - cu[tid]);
    }

    // stage finalized gelu(E@W1+b1) transposed: 5 strided rounds, each
    // 4 independent float4 partial reads + b1 (R7 pattern, full K).
    {
        const float4* P0 = (const float4*)&g_part1[0][0][0];
        const float4* P1 = (const float4*)&g_part1[1][0][0];
        const float4* P2 = (const float4*)&g_part1[2][0][0];
        const float4* P3 = (const float4*)&g_part1[3][0][0];
        const float4* B1 = (const float4*)b1;
#pragma unroll
        for (int r = 0; r < 5; r++) {
            const int i = r * TPB + tid;           // float4 index in [V][D]
            if (i < V * (D / 4)) {
                const int v = i >> 7;              // D/4 = 128
                const int q = i & 127;
                const float4 a = P0[i];
                const float4 b = P1[i];
                const float4 c = P2[i];
                const float4 d = P3[i];
                const float4 bb = B1[q];
                float x0 = bb.x + a.x + b.x + c.x + d.x;
                float x1 = bb.y + a.y + b.y + c.y + d.y;
                float x2 = bb.z + a.z + b.z + c.z + d.z;
                float x3 = bb.w + a.w + b.w + c.w + d.w;
                x0 = 0.5f * x0 * (1.0f + erff(x0 * 0.70710678118654752f));
                x1 = 0.5f * x1 * (1.0f + erff(x1 * 0.70710678118654752f));
                x2 = 0.5f * x2 * (1.0f + erff(x2 * 0.70710678118654752f));
                x3 = 0.5f * x3 * (1.0f + erff(x3 * 0.70710678118654752f));
                const int k = q * 4;
                etr[(k + 0) * EPAD + v] = x0;
                etr[(k + 1) * EPAD + v] = x1;
                etr[(k + 2) * EPAD + v] = x2;
                etr[(k + 3) * EPAD + v] = x3;
            }
        }
    }
    __syncthreads();

    float acc[V];
#pragma unroll
    for (int v = 0; v < V; v++) acc[v] = 0.0f;

    const float* wp = W2 + (size_t)(ty * 8) * D + jbase + jl;
    float w[8];
#pragma unroll
    for (int kk = 0; kk < 8; kk++) w[kk] = wp[kk * D];

#pragma unroll
    for (int kk = 0; kk < 8; kk++) {
        const float* er = &etr[(ty * 8 + kk) * EPAD];
        const float4 e0 = *(const float4*)(er);
        const float4 e1 = *(const float4*)(er + 4);
        const float4 e2 = *(const float4*)(er + 8);
        const float4 e3 = *(const float4*)(er + 12);
        const float  ee = er[16];
        const float  wv = w[kk];
        acc[0]  += e0.x * wv;  acc[1]  += e0.y * wv;
        acc[2]  += e0.z * wv;  acc[3]  += e0.w * wv;
        acc[4]  += e1.x * wv;  acc[5]  += e1.y * wv;
        acc[6]  += e1.z * wv;  acc[7]  += e1.w * wv;
        acc[8]  += e2.x * wv;  acc[9]  += e2.y * wv;
        acc[10] += e2.z * wv;  acc[11] += e2.w * wv;
        acc[12] += e3.x * wv;  acc[13] += e3.y * wv;
        acc[14] += e3.z * wv;  acc[15] += e3.w * wv;
        acc[16] += ee   * wv;
    }
    __syncthreads();           // done reading etr; reuse as reduction buffer

    float* red = etr;          // [64][V*8] = 8704 floats
#pragma unroll
    for (int v = 0; v < V; v++) red[ty * (V * 8) + v * 8 + jl] = acc[v];
    __syncthreads();

    if (tid < V * 8) {
        float s = b2[jbase + (tid & 7)];
#pragma unroll
        for (int g = 0; g < 64; g++) s += red[g * (V * 8) + tid];
        Ht[tid] = s;
    }
    __syncthreads();

    const int s = tid >> 3;
    if (s < n_segs) {
        const float* f = &fcs[s * 18];
        float a = 0.0f;
#pragma unroll
        for (int v = 0; v < V; v++) a += f[v] * Ht[v * 8 + jl];
        out[s * D + jbase + jl] = a * inv[s];
    }
}

// ---------------------------------------------------------------------------
extern "C" void kernel_launch(void* const* d_in, const int* in_sizes, int n_in,
                              void* d_out, int out_size) {
    const int*   tok = (const int*)  d_in[0];
    const int*   cu  = (const int*)  d_in[1];
    const float* E   = (const float*)d_in[2];
    const float* W1  = (const float*)d_in[3];
    const float* b1  = (const float*)d_in[4];
    const float* W2  = (const float*)d_in[5];
    const float* b2  = (const float*)d_in[6];
    float*       out = (float*)d_out;

    int n_segs = in_sizes[1] - 1;
    if (n_segs > MAX_SEGS) n_segs = MAX_SEGS;

    k1<<<64 + n_segs, TPB>>>(E, W1, tok, cu, n_segs);
    k2<<<64, TPB>>>(W2, b1, b2, cu, out, n_segs);
}